// round 8
// baseline (speedup 1.0000x reference)
#include <cuda_runtime.h>

#define IN_DIM   8192
#define OUT_DIM  16384
#define TOPK     327
#define ROW_SPLITS 37                 // 16 * 37 = 592 = 4 * 148 SMs → one even wave
#define ROWS_PER_SPLIT 222            // ceil(8192 / 37)
#define COL_BLOCKS 16                 // 16 blocks * 256 thr * 4 cols = 16384 cols
#define CNT_ONE  (1u << 20)           // arrival counter packed above the value
#define VAL_MASK 0xFFFFFu             // overlap value ≤ 8192 fits easily

__device__ unsigned g_overlap[OUT_DIM];   // [counter:12 | value:20]; zeroed at load & by finalize
__device__ int      g_hist[IN_DIM + 1];   // zeroed at load & by finalize

__device__ __forceinline__ int warp_incl_scan(int v) {
    int lane = threadIdx.x & 31;
#pragma unroll
    for (int o = 1; o < 32; o <<= 1) {
        int n = __shfl_up_sync(0xffffffffu, v, o);
        if (lane >= o) v += n;
    }
    return v;
}

// ---------------------------------------------------------------------------
// Kernel 1: binarized GEMV with fused histogram.
// Each block compacts its own x-slice, streams active rows of p (evict-first),
// accumulates 4 columns/thread, then does UNCONDITIONAL packed atomicAdds.
// The 37th (last) arrival per column publishes the final value to g_hist.
// round(p) for p ~ U[0,1) under round-half-even == (p > 0.5f).
// ---------------------------------------------------------------------------
__global__ void __launch_bounds__(256, 4)
gemv_kernel(const float* __restrict__ p, const int* __restrict__ x) {
    __shared__ int s_act[ROWS_PER_SPLIT];
    __shared__ int s_wbase[8];
    __shared__ int s_na;

    int t    = threadIdx.x;
    int lane = t & 31;
    int w    = t >> 5;

    int r0 = blockIdx.y * ROWS_PER_SPLIT;
    int r1 = min(r0 + ROWS_PER_SPLIT, IN_DIM);
    int n  = r1 - r0;

    // --- per-block ordered compaction of the x slice ---
    int flag = 0;
    if (t < n) flag = (x[r0 + t] != 0);
    unsigned m = __ballot_sync(0xffffffffu, flag);
    int pos = __popc(m & ((1u << lane) - 1u));
    if (lane == 0) s_wbase[w] = __popc(m);
    __syncthreads();
    if (t < 8) {
        int v = s_wbase[t];
        int inc = v;
#pragma unroll
        for (int o = 1; o < 8; o <<= 1) {
            int u = __shfl_up_sync(0xffu, inc, o);
            if (t >= o) inc += u;
        }
        s_wbase[t] = inc - v;              // exclusive base
        if (t == 7) s_na = inc;
    }
    __syncthreads();
    if (flag) s_act[s_wbase[w] + pos] = r0 + t;
    __syncthreads();

    int na = s_na;

    // --- stream active rows, 8-deep for MLP, evict-first loads ---
    int col = (blockIdx.x * blockDim.x + t) * 4;
    const float4* pc = reinterpret_cast<const float4*>(p + col);

    unsigned c0 = 0, c1 = 0, c2 = 0, c3 = 0;
    int r = 0;
    for (; r + 8 <= na; r += 8) {
        float4 v[8];
#pragma unroll
        for (int u = 0; u < 8; u++)
            v[u] = __ldcs(pc + (size_t)s_act[r + u] * (OUT_DIM / 4));
#pragma unroll
        for (int u = 0; u < 8; u++) {
            c0 += (v[u].x > 0.5f);
            c1 += (v[u].y > 0.5f);
            c2 += (v[u].z > 0.5f);
            c3 += (v[u].w > 0.5f);
        }
    }
    for (; r < na; r++) {
        float4 v0 = __ldcs(pc + (size_t)s_act[r] * (OUT_DIM / 4));
        c0 += (v0.x > 0.5f);
        c1 += (v0.y > 0.5f);
        c2 += (v0.z > 0.5f);
        c3 += (v0.w > 0.5f);
    }

    // --- packed accumulate; last arrival publishes to histogram ---
    unsigned cc[4] = {c0, c1, c2, c3};
#pragma unroll
    for (int u = 0; u < 4; u++) {
        unsigned old = atomicAdd(&g_overlap[col + u], CNT_ONE + cc[u]);
        if ((old >> 20) == (ROW_SPLITS - 1)) {
            int final_v = (int)((old & VAL_MASK) + cc[u]);
            atomicAdd(&g_hist[final_v], 1);
        }
    }
}

// ---------------------------------------------------------------------------
// Kernel 2: threshold from prebuilt histogram + exact jax.lax.top_k tie
// semantics (lower index first). Single block, 1024 threads. Re-zeroes
// g_overlap and g_hist at the end (deterministic across graph replays).
// ---------------------------------------------------------------------------
__global__ void __launch_bounds__(1024)
topk_kernel(float* __restrict__ out) {
    __shared__ int s_hist[IN_DIM + 1];   // 8193 bins
    __shared__ int s_scan[1024];
    __shared__ int s_warp[32];
    __shared__ int s_cnt[512];           // per (segment, warp) tie counts
    __shared__ int s_T, s_R;

    int tid  = threadIdx.x;
    int lane = tid & 31;
    int wid  = tid >> 5;

    for (int i = tid; i <= IN_DIM; i += 1024) s_hist[i] = g_hist[i];

    // overlap values (masked) — load early for latency overlap
    int ov[16];
#pragma unroll
    for (int s = 0; s < 16; s++)
        ov[s] = (int)(g_overlap[s * 1024 + tid] & VAL_MASK);
    __syncthreads();

    // --- Phase B: threshold search ---
    // thread t owns bins [8t, 8t+7]; thread 1023 also owns bin 8192.
    int b0 = tid * 8;
    int csum = 0;
#pragma unroll
    for (int k = 0; k < 8; k++) csum += s_hist[b0 + k];
    if (tid == 1023) csum += s_hist[IN_DIM];

    // reversed inclusive scan => suffix sums
    s_scan[1023 - tid] = csum;
    __syncthreads();
    {
        int v = s_scan[tid];
        int inc = warp_incl_scan(v);
        if (lane == 31) s_warp[wid] = inc;
        __syncthreads();
        if (wid == 0) {
            int wv = s_warp[lane];
            s_warp[lane] = warp_incl_scan(wv);
        }
        __syncthreads();
        int add = (wid > 0) ? s_warp[wid - 1] : 0;
        s_scan[tid] = inc + add;
    }
    __syncthreads();

    int above = (tid == 1023) ? 0 : s_scan[1022 - tid];

    {
        int running = above;
        int top = (tid == 1023) ? IN_DIM : (b0 + 7);
        for (int v = top; v >= b0; v--) {
            int prev = running;              // count(> v)
            running += s_hist[v];            // count(>= v)
            if (prev < TOPK && running >= TOPK) {
                s_T = v;
                s_R = TOPK - prev;           // tie slots at value T
            }
        }
    }
    __syncthreads();

    int T = s_T;
    int R = s_R;

    // --- Phase C: ordered tie resolution via ballot + one 512-entry scan ---
    // (ballots are recomputed in the output loop to keep register count low)
#pragma unroll
    for (int s = 0; s < 16; s++) {
        unsigned m = __ballot_sync(0xffffffffu, ov[s] == T);
        if (lane == 0) s_cnt[s * 32 + wid] = __popc(m);
    }
    __syncthreads();

    int v512 = 0, inc512 = 0;
    if (tid < 512) {
        v512 = s_cnt[tid];
        inc512 = warp_incl_scan(v512);
        if (lane == 31) s_warp[wid] = inc512;   // wid 0..15
    }
    __syncthreads();
    if (tid < 32) {
        int wv = (tid < 16) ? s_warp[tid] : 0;
        s_warp[tid] = warp_incl_scan(wv);
    }
    __syncthreads();
    if (tid < 512) {
        int add = (wid > 0) ? s_warp[wid - 1] : 0;
        s_cnt[tid] = inc512 - v512 + add;       // exclusive prefix
    }
    __syncthreads();

    unsigned lt = (1u << lane) - 1u;
#pragma unroll
    for (int s = 0; s < 16; s++) {
        int flag = (ov[s] == T);
        unsigned m = __ballot_sync(0xffffffffu, flag);
        int rank = s_cnt[s * 32 + wid] + __popc(m & lt);
        float val = 0.0f;
        if (ov[s] > T) val = 1.0f;
        else if (flag && rank < R) val = 1.0f;
        out[s * 1024 + tid] = val;
    }

    // --- reset accumulators for the next launch (deterministic invariant) ---
#pragma unroll
    for (int s = 0; s < 16; s++) g_overlap[s * 1024 + tid] = 0u;
    for (int i = tid; i <= IN_DIM; i += 1024) g_hist[i] = 0;
}

extern "C" void kernel_launch(void* const* d_in, const int* in_sizes, int n_in,
                              void* d_out, int out_size) {
    const int*   x = (const int*)d_in[0];
    const float* p = (const float*)d_in[1];
    if (in_sizes[0] != IN_DIM) {
        x = (const int*)d_in[1];
        p = (const float*)d_in[0];
    }
    float* out = (float*)d_out;

    dim3 grid(COL_BLOCKS, ROW_SPLITS);
    gemv_kernel<<<grid, 256>>>(p, x);
    topk_kernel<<<1, 1024>>>(out);
}